// round 12
// baseline (speedup 1.0000x reference)
#include <cuda_runtime.h>
#include <math.h>

// Router split into two kernels:
//  K1 (pool):  patch (32768,32,8,8) f32 -> per-channel means into 4MB scratch.
//              Pure streaming reduction, ~zero compute tail, max occupancy.
//  K2 (route): scratch (32768,32) -> weights_filtered (32768,16).
//              2 patches per warp (half-warp parallel post-phase).

#define EXPERTS 16
#define CHANNELS 32
#define MAX_PATCHES 32768
#define PATCH_F4 512            // 32*64 floats / 4

__device__ float g_emb[MAX_PATCHES * CHANNELS];   // 4MB scratch (means)

// ---------------------------------------------------------------------------
// Kernel 1: pooling. Thread t handles 4 consecutive float4 (64B) — exactly one
// quarter of one channel. 4 threads per channel; shfl_xor{1,2} combine.
// Lanes 0-7 compact-store the warp's 8 channel means (32B coalesced).
// ---------------------------------------------------------------------------
__global__ __launch_bounds__(256) void pool_kernel(
    const float* __restrict__ patch, int n_f4)
{
    const int gid  = blockIdx.x * 256 + threadIdx.x;
    const int base = gid * 4;
    if (base >= n_f4) return;

    const float4* p4 = reinterpret_cast<const float4*>(patch);
    float s = 0.0f;
#pragma unroll
    for (int i = 0; i < 4; i++) {
        float4 t = __ldcs(&p4[base + i]);
        s += (t.x + t.y) + (t.z + t.w);
    }
    // Combine the 4 threads covering this channel.
    s += __shfl_xor_sync(0xFFFFFFFFu, s, 1);
    s += __shfl_xor_sync(0xFFFFFFFFu, s, 2);
    // Warp covers 8 consecutive channels; lanes 0-7 store them contiguously.
    const int lane = threadIdx.x & 31;
    const float v = __shfl_sync(0xFFFFFFFFu, s, (lane & 7) * 4);
    if (lane < 8) {
        const int g_base = ((gid & ~31) >> 2);    // first channel-id of warp
        g_emb[g_base + lane] = v * (1.0f / 64.0f);
    }
}

// ---------------------------------------------------------------------------
// Kernel 2: routing. One warp = 2 patches; A in lanes 0-15, B in lanes 16-31.
// All reductions use xor masks {8,4,2,1} (stay within each half-warp).
// ---------------------------------------------------------------------------
#define WARPS_PER_BLOCK 8
#define THREADS (WARPS_PER_BLOCK * 32)

__global__ __launch_bounds__(THREADS) void route_kernel(
    const float* __restrict__ keys,
    const float* __restrict__ temp_p,
    const float* __restrict__ beta_p,
    const float* __restrict__ thr_p,
    float* __restrict__ out,
    int n_patches)
{
    __shared__ float keys_s[EXPERTS * 33];        // natural channel order, padded
    __shared__ float buf[WARPS_PER_BLOCK][64];

    const int tid  = threadIdx.x;
    const int wid  = tid >> 5;
    const int lane = tid & 31;

    for (int i = tid; i < EXPERTS * CHANNELS; i += THREADS) {
        int e = i >> 5, c = i & 31;
        keys_s[e * 33 + c] = keys[i];
    }

    const float inv_temp = 1.0f / (*temp_p);
    const float beta     = (*beta_p) + 1e-8f;
    const float thr      = *thr_p;
    __syncthreads();

    const int pid = 2 * (blockIdx.x * WARPS_PER_BLOCK + wid);
    if (pid >= n_patches) return;
    const bool has_b = (pid + 1) < n_patches;

    // ---- Load both embeddings (64 floats, coalesced 256B per warp).
    const float* eb = &g_emb[(size_t)pid * CHANNELS];
    const float eA = eb[lane];
    const float eB = eb[(has_b ? 32 : 0) + lane];
    buf[wid][lane]      = eA;
    buf[wid][32 + lane] = eB;

    // ---- Norms (full-warp butterflies over each patch's 32 channels).
    float sqA = eA * eA;
    float sqB = eB * eB;
#pragma unroll
    for (int k = 16; k; k >>= 1) {
        sqA += __shfl_xor_sync(0xFFFFFFFFu, sqA, k);
        sqB += __shfl_xor_sync(0xFFFFFFFFu, sqB, k);
    }
    const float inv_n = 1.0f / fmaxf(sqrtf((lane & 16) ? sqB : sqA), 1e-12f);
    __syncwarp();

    // ---- Logits: lanes 0-15 -> patch A experts, lanes 16-31 -> patch B.
    const float* cbase = &buf[wid][(lane & 16) << 1];   // 0 or 32
    const float* kr    = &keys_s[(lane & 15) * 33];
    float logit = 0.0f;
#pragma unroll
    for (int c = 0; c < CHANNELS; c++)
        logit = fmaf(cbase[c], kr[c], logit);
    __syncwarp();

    const float sl = logit * inv_n * inv_temp + 1e-8f;

    // ---- Softmax (per 16-lane half) ----
    float mx = sl;
#pragma unroll
    for (int k = 8; k; k >>= 1) mx = fmaxf(mx, __shfl_xor_sync(0xFFFFFFFFu, mx, k));
    float ew = __expf(sl - mx);
    float denom = ew;
#pragma unroll
    for (int k = 8; k; k >>= 1) denom += __shfl_xor_sync(0xFFFFFFFFu, denom, k);
    const float w = ew / denom;

    // ---- Moments / entropy (per half) ----
    float sw   = w;
    float swsq = w * w;
    float swl  = w * __logf(w + 1e-18f);
#pragma unroll
    for (int k = 8; k; k >>= 1) {
        sw   += __shfl_xor_sync(0xFFFFFFFFu, sw,   k);
        swsq += __shfl_xor_sync(0xFFFFFFFFu, swsq, k);
        swl  += __shfl_xor_sync(0xFFFFFFFFu, swl,  k);
    }

    // ---- Descending sort via rank, per half (stable tie-break by slot) ----
    buf[wid][lane] = w;
    __syncwarp();
    const int base = lane & 16;
    {
        int rank = 0;
#pragma unroll
        for (int j = 0; j < EXPERTS; j++) {
            float wj = buf[wid][base + j];
            rank += (wj > w) || (wj == w && (base + j) < lane);
        }
        buf[wid][32 + base + rank] = w;
    }
    __syncwarp();

    const float s0 = buf[wid][32 + base + 0];
    const float s1 = buf[wid][32 + base + 1];
    const float s2 = buf[wid][32 + base + 2];
    const float s3 = buf[wid][32 + base + 3];
    const float s4 = buf[wid][32 + base + 4];

    // ---- Adaptive threshold ----
    const float mean    = sw * (1.0f / 16.0f);
    const float var     = fmaxf(0.0f, (swsq - sw * sw * (1.0f / 16.0f)) * (1.0f / 15.0f));
    const float stdw    = sqrtf(var);
    const float entropy = -swl;

    const float max_comp = 1.0f - s0;
    const float ent_comp = 1.0f - entropy * 0.360673760222f;  // 1/ln(16)
    const float mean_rest = (s1 + s2 + s3 + s4) * 0.25f;
    float gap = (s0 - mean_rest) / (s0 + 1e-8f);
    gap = fminf(fmaxf(gap, 0.0f), 1.0f);

    float adaptive = thr * (0.5f + 0.4f * max_comp + 0.3f * ent_comp + 0.3f * gap);
    const float min_thr = fmaxf(0.05f, mean - 0.5f * stdw);
    const float max_thr = fminf(0.7f, s0 - 0.1f * stdw);
    adaptive = fminf(fmaxf(adaptive, min_thr), max_thr);
    adaptive = fminf(adaptive, s3 * 0.9f);

    // ---- Soft mask, filter, renormalize (per half) ----
    const float mask = 1.0f / (1.0f + __expf(-beta * (w - adaptive)));
    float wf = w * mask;
    float swf = wf;
#pragma unroll
    for (int k = 8; k; k >>= 1) swf += __shfl_xor_sync(0xFFFFFFFFu, swf, k);
    const float o = wf / fmaxf(swf, 1e-8f);

    // Full-warp coalesced 128B store.
    if (lane < 16 || has_b)
        out[(size_t)pid * EXPERTS + lane] = o;
}

extern "C" void kernel_launch(void* const* d_in, const int* in_sizes, int n_in,
                              void* d_out, int out_size)
{
    const float* patch  = (const float*)d_in[0];
    const float* keys   = (const float*)d_in[1];
    const float* temp_p = (const float*)d_in[2];
    const float* beta_p = (const float*)d_in[3];
    const float* thr_p  = (const float*)d_in[4];
    float* out = (float*)d_out;

    const int n_patches = in_sizes[0] / (CHANNELS * 64);   // 32768
    const int n_f4      = n_patches * PATCH_F4;

    // K1: one thread per 4 float4.
    const int k1_threads = n_f4 / 4;
    const int k1_blocks  = (k1_threads + 255) / 256;
    pool_kernel<<<k1_blocks, 256>>>(patch, n_f4);

    // K2: one warp per 2 patches.
    const int k2_blocks = (n_patches + 2 * WARPS_PER_BLOCK - 1) / (2 * WARPS_PER_BLOCK);
    route_kernel<<<k2_blocks, THREADS>>>(keys, temp_p, beta_p, thr_p, out, n_patches);
}

// round 14
// speedup vs baseline: 1.0543x; 1.0543x over previous
#include <cuda_runtime.h>
#include <math.h>
#include <float.h>

// Router split into two kernels:
//  K1 (pool):  patch (32768,32,8,8) f32 -> per-channel means into 4MB scratch.
//              Pure streaming reduction, ~zero compute tail (83% HBM).
//  K2 (route): scratch (32768,32) -> weights_filtered (32768,16).
//              ONE THREAD PER PATCH: all 16-wide math scalar in registers,
//              no shfl/sync/smem-scratch. ~9x fewer instructions per patch.

#define EXPERTS 16
#define CHANNELS 32
#define MAX_PATCHES 32768
#define PATCH_F4 512            // 32*64 floats / 4

__device__ __align__(16) float g_emb[MAX_PATCHES * CHANNELS];   // 4MB scratch

// ---------------------------------------------------------------------------
// Kernel 1: pooling. Thread t handles 4 consecutive float4 (64B) — one
// quarter of one channel. shfl_xor{1,2} combine; lanes 0-7 store 32B runs.
// ---------------------------------------------------------------------------
__global__ __launch_bounds__(256) void pool_kernel(
    const float* __restrict__ patch, int n_f4)
{
    const int gid  = blockIdx.x * 256 + threadIdx.x;
    const int base = gid * 4;
    if (base >= n_f4) return;

    const float4* p4 = reinterpret_cast<const float4*>(patch);
    float s = 0.0f;
#pragma unroll
    for (int i = 0; i < 4; i++) {
        float4 t = __ldcs(&p4[base + i]);
        s += (t.x + t.y) + (t.z + t.w);
    }
    s += __shfl_xor_sync(0xFFFFFFFFu, s, 1);
    s += __shfl_xor_sync(0xFFFFFFFFu, s, 2);
    const int lane = threadIdx.x & 31;
    const float v = __shfl_sync(0xFFFFFFFFu, s, (lane & 7) * 4);
    if (lane < 8) {
        const int g_base = ((gid & ~31) >> 2);    // first channel-id of warp
        g_emb[g_base + lane] = v * (1.0f / 64.0f);
    }
}

// ---------------------------------------------------------------------------
// Kernel 2: routing, one thread per patch.
// ---------------------------------------------------------------------------
#define K2_THREADS 128

__global__ __launch_bounds__(K2_THREADS) void route_kernel(
    const float* __restrict__ keys,
    const float* __restrict__ temp_p,
    const float* __restrict__ beta_p,
    const float* __restrict__ thr_p,
    float* __restrict__ out,
    int n_patches)
{
    // Keys: natural order, row stride 36 floats (144B, 16B-aligned) so rows
    // can be read as float4; all lanes read the same address -> broadcast.
    __shared__ __align__(16) float keys_s[EXPERTS * 36];

    const int tid = threadIdx.x;
    for (int i = tid; i < EXPERTS * CHANNELS; i += K2_THREADS) {
        int e = i >> 5, c = i & 31;
        keys_s[e * 36 + c] = keys[i];
    }

    const float inv_temp = 1.0f / (*temp_p);
    const float beta     = (*beta_p) + 1e-8f;
    const float thr      = *thr_p;
    __syncthreads();

    const int pid = blockIdx.x * K2_THREADS + tid;
    if (pid >= n_patches) return;

    // ---- Load this patch's 32-channel embedding (8 x LDG.128, L2-resident).
    float e[CHANNELS];
    const float4* ep = reinterpret_cast<const float4*>(&g_emb[(size_t)pid * CHANNELS]);
#pragma unroll
    for (int i = 0; i < 8; i++) {
        float4 t = ep[i];
        e[4 * i + 0] = t.x; e[4 * i + 1] = t.y;
        e[4 * i + 2] = t.z; e[4 * i + 3] = t.w;
    }

    // ---- Norm ----
    float sq = 0.0f;
#pragma unroll
    for (int c = 0; c < CHANNELS; c++) sq = fmaf(e[c], e[c], sq);
    const float scale = (1.0f / fmaxf(sqrtf(sq), 1e-12f)) * inv_temp;

    // ---- Logits (16 dots; keys broadcast from smem as float4) ----
    float w[EXPERTS];
#pragma unroll
    for (int ex = 0; ex < EXPERTS; ex++) {
        const float4* kr = reinterpret_cast<const float4*>(&keys_s[ex * 36]);
        float acc = 0.0f;
#pragma unroll
        for (int i = 0; i < 8; i++) {
            float4 k4 = kr[i];
            acc = fmaf(e[4 * i + 0], k4.x, acc);
            acc = fmaf(e[4 * i + 1], k4.y, acc);
            acc = fmaf(e[4 * i + 2], k4.z, acc);
            acc = fmaf(e[4 * i + 3], k4.w, acc);
        }
        w[ex] = acc * scale + 1e-8f;          // scaled logits
    }

    // ---- Softmax ----
    float mx = w[0];
#pragma unroll
    for (int ex = 1; ex < EXPERTS; ex++) mx = fmaxf(mx, w[ex]);
    float denom = 0.0f;
#pragma unroll
    for (int ex = 0; ex < EXPERTS; ex++) { w[ex] = __expf(w[ex] - mx); denom += w[ex]; }
    const float inv_d = 1.0f / denom;
#pragma unroll
    for (int ex = 0; ex < EXPERTS; ex++) w[ex] *= inv_d;

    // ---- Moments / entropy ----
    float sw = 0.0f, swsq = 0.0f, swl = 0.0f;
#pragma unroll
    for (int ex = 0; ex < EXPERTS; ex++) {
        sw   += w[ex];
        swsq  = fmaf(w[ex], w[ex], swsq);
        swl   = fmaf(w[ex], __logf(w[ex] + 1e-18f), swl);
    }

    // ---- Branchless top-5 (only s0..s4 are consumed) ----
    float s0 = -FLT_MAX, s1 = -FLT_MAX, s2 = -FLT_MAX, s3 = -FLT_MAX, s4 = -FLT_MAX;
#pragma unroll
    for (int ex = 0; ex < EXPERTS; ex++) {
        float v = w[ex], b;
        b = fmaxf(s0, v); v = fminf(s0, v); s0 = b;
        b = fmaxf(s1, v); v = fminf(s1, v); s1 = b;
        b = fmaxf(s2, v); v = fminf(s2, v); s2 = b;
        b = fmaxf(s3, v); v = fminf(s3, v); s3 = b;
        s4 = fmaxf(s4, v);
    }

    // ---- Adaptive threshold ----
    const float mean    = sw * (1.0f / 16.0f);
    const float var     = fmaxf(0.0f, (swsq - sw * sw * (1.0f / 16.0f)) * (1.0f / 15.0f));
    const float stdw    = sqrtf(var);
    const float entropy = -swl;

    const float max_comp = 1.0f - s0;
    const float ent_comp = 1.0f - entropy * 0.360673760222f;  // 1/ln(16)
    const float mean_rest = (s1 + s2 + s3 + s4) * 0.25f;
    float gap = (s0 - mean_rest) / (s0 + 1e-8f);
    gap = fminf(fmaxf(gap, 0.0f), 1.0f);

    float adaptive = thr * (0.5f + 0.4f * max_comp + 0.3f * ent_comp + 0.3f * gap);
    const float min_thr = fmaxf(0.05f, mean - 0.5f * stdw);
    const float max_thr = fminf(0.7f, s0 - 0.1f * stdw);
    adaptive = fminf(fmaxf(adaptive, min_thr), max_thr);
    adaptive = fminf(adaptive, s3 * 0.9f);          // kth = sorted[3]

    // ---- Soft mask, filter, renormalize ----
    float swf = 0.0f;
#pragma unroll
    for (int ex = 0; ex < EXPERTS; ex++) {
        const float mask = 1.0f / (1.0f + __expf(-beta * (w[ex] - adaptive)));
        w[ex] *= mask;
        swf += w[ex];
    }
    const float inv_s = 1.0f / fmaxf(swf, 1e-8f);

    // ---- Coalesced-enough vector store: 4 x STG.128 ----
    float4* o4 = reinterpret_cast<float4*>(&out[(size_t)pid * EXPERTS]);
#pragma unroll
    for (int j = 0; j < 4; j++)
        o4[j] = make_float4(w[4 * j + 0] * inv_s, w[4 * j + 1] * inv_s,
                            w[4 * j + 2] * inv_s, w[4 * j + 3] * inv_s);
}

extern "C" void kernel_launch(void* const* d_in, const int* in_sizes, int n_in,
                              void* d_out, int out_size)
{
    const float* patch  = (const float*)d_in[0];
    const float* keys   = (const float*)d_in[1];
    const float* temp_p = (const float*)d_in[2];
    const float* beta_p = (const float*)d_in[3];
    const float* thr_p  = (const float*)d_in[4];
    float* out = (float*)d_out;

    const int n_patches = in_sizes[0] / (CHANNELS * 64);   // 32768
    const int n_f4      = n_patches * PATCH_F4;

    // K1: one thread per 4 float4.
    const int k1_threads = n_f4 / 4;
    const int k1_blocks  = (k1_threads + 255) / 256;
    pool_kernel<<<k1_blocks, 256>>>(patch, n_f4);

    // K2: one thread per patch.
    const int k2_blocks = (n_patches + K2_THREADS - 1) / K2_THREADS;
    route_kernel<<<k2_blocks, K2_THREADS>>>(keys, temp_p, beta_p, thr_p, out, n_patches);
}